// round 1
// baseline (speedup 1.0000x reference)
#include <cuda_runtime.h>

#define NCONF   8
#define NATOMS  10
#define NSTATES 4
#define NBASIS  24
#define HIDDEN  48
#define PPC     (NATOMS*(NATOMS-1))   // 90 pairs per configuration
#define NDIR    (NCONF*NATOMS*3)      // 240 perturbation directions

#define PI_F    3.14159265358979323846f
#define CUT     6.0f
#define ALPHA_F 1.5f

// scratch (no cudaMalloc allowed)
__device__ float g_B[NCONF*NATOMS*3*NSTATES];  // dT_s/dx  per (c,a,mu,s)
__device__ float g_H[NCONF*NATOMS*3*NSTATES];  // d2T_s/dx2 per (c,a,mu,s)
__device__ float g_T[NCONF*NSTATES];           // T_s values per config

// ---------------- second-order Taylor jet ----------------
struct J { float v, d, h; };  // value, 1st deriv, 2nd deriv

__device__ __forceinline__ J jadd(J a, J b){ return {a.v+b.v, a.d+b.d, a.h+b.h}; }
__device__ __forceinline__ J jmul(J a, J b){
    return {a.v*b.v, a.v*b.d + a.d*b.v, a.v*b.h + 2.0f*a.d*b.d + a.h*b.v};
}
__device__ __forceinline__ J jscale(J a, float s){ return {a.v*s, a.d*s, a.h*s}; }
__device__ __forceinline__ J jchain(float f, float f1, float f2, J x){
    return {f, f1*x.d, f1*x.h + f2*x.d*x.d};
}
__device__ __forceinline__ J jsqrt(J x){
    float f = sqrtf(x.v); float f1 = 0.5f/f; float f2 = -0.25f/(x.v*f);
    return jchain(f, f1, f2, x);
}
__device__ __forceinline__ J jexp(J x){ float f = expf(x.v); return jchain(f, f, f, x); }
__device__ __forceinline__ J jsin(J x){ float s=sinf(x.v), c=cosf(x.v); return jchain(s, c, -s, x); }
__device__ __forceinline__ J jcos(J x){ float s=sinf(x.v), c=cosf(x.v); return jchain(c, -s, -c, x); }
__device__ __forceinline__ J jtanh(J x){
    float t = tanhf(x.v); float f1 = 1.0f - t*t;
    return jchain(t, f1, -2.0f*t*f1, x);
}

// ---------------- kernel A: one block per (config, atom, mu) direction ----------------
__global__ void __launch_bounds__(128)
wave_hess_kernel(const float* __restrict__ cart, const int* __restrict__ species,
                 const int* __restrict__ ai, const float* __restrict__ shifts,
                 const float* __restrict__ W1, const float* __restrict__ B1,
                 const float* __restrict__ W2, const float* __restrict__ Emb,
                 int npairs)
{
    const int bid  = blockIdx.x;
    const int c    = bid / (NATOMS*3);
    const int rem  = bid % (NATOMS*3);
    const int aLoc = rem / 3;
    const int mu   = rem % 3;
    const int A    = c*NATOMS + aLoc;     // perturbed global atom
    const int tid  = threadIdx.x;

    __shared__ int s_i[PPC], s_j[PPC];               // local atom ids per pair
    __shared__ J   s_dist[PPC], s_fcut[PPC], s_rad[PPC];
    __shared__ int s_plist[NATOMS][NATOMS-1];        // pairs grouped by center atom
    __shared__ J   s_dens[NATOMS][NBASIS];
    __shared__ J   s_hid[NATOMS][HIDDEN];
    __shared__ J   s_p[NATOMS][NSTATES];
    __shared__ float s_term[PPC][NSTATES][3];

    // Phase 1: pair geometry jets (perturbation on x_{A,mu})
    if (tid < PPC) {
        int pg = c*PPC + tid;
        int gi = ai[pg];
        int gj = ai[npairs + pg];
        s_i[tid] = gi - c*NATOMS;
        s_j[tid] = gj - c*NATOMS;
        J d2 = {0.f, 0.f, 0.f};
        #pragma unroll
        for (int nu = 0; nu < 3; nu++) {
            float av = cart[gj*3+nu] + shifts[pg*3+nu] - cart[gi*3+nu];
            float bd = ((gj==A && nu==mu) ? 1.f : 0.f) - ((gi==A && nu==mu) ? 1.f : 0.f);
            J dv = {av, bd, 0.f};
            d2 = jadd(d2, jmul(dv, dv));
        }
        J dist = jsqrt(d2);
        s_dist[tid] = dist;
        // cosine cutoff on min(dist, CUT) — clamp kills derivatives past cutoff
        J dm = (dist.v < CUT) ? dist : J{CUT, 0.f, 0.f};
        J fc = jscale(jcos(jscale(dm, PI_F/CUT)), 0.5f);
        fc.v += 0.5f;
        s_fcut[tid] = fc;
        // radial = sin(dist*pi/CUT)^3  (no clamp, matches reference)
        J sn = jsin(jscale(dist, PI_F/CUT));
        s_rad[tid] = jmul(sn, jmul(sn, sn));
    }
    __syncthreads();

    // Phase 2: deterministic per-atom pair lists
    if (tid < NATOMS) {
        int cnt = 0;
        for (int p = 0; p < PPC; p++)
            if (s_i[p] == tid) s_plist[tid][cnt++] = p;
    }
    __syncthreads();

    // Phase 3: density jets (atom, basis) items
    for (int item = tid; item < NATOMS*NBASIS; item += blockDim.x) {
        int at = item / NBASIS, b = item % NBASIS;
        float center = CUT * (float)b / (float)(NBASIS - 1);
        J acc = {0.f, 0.f, 0.f};
        #pragma unroll
        for (int k = 0; k < NATOMS-1; k++) {
            int p = s_plist[at][k];
            J t = s_dist[p]; t.v -= center;
            J e = jexp(jscale(jmul(t, t), -ALPHA_F));
            acc = jadd(acc, jmul(e, s_fcut[p]));
        }
        s_dens[at][b] = acc;
    }
    __syncthreads();

    // Phase 4: hidden layer jets
    for (int item = tid; item < NATOMS*HIDDEN; item += blockDim.x) {
        int at = item / HIDDEN, hh = item % HIDDEN;
        int sp = species[c*NATOMS + at];
        J u = {B1[sp*HIDDEN + hh], 0.f, 0.f};
        #pragma unroll
        for (int b = 0; b < NBASIS; b++) {
            float w = W1[b*HIDDEN + hh];
            J dn = s_dens[at][b];
            u.v = fmaf(dn.v, w, u.v);
            u.d = fmaf(dn.d, w, u.d);
            u.h = fmaf(dn.h, w, u.h);
        }
        s_hid[at][hh] = jtanh(u);
    }
    __syncthreads();

    // Phase 5: initpsi jets
    for (int item = tid; item < NATOMS*NSTATES; item += blockDim.x) {
        int at = item / NSTATES, s = item % NSTATES;
        int sp = species[c*NATOMS + at];
        J p = {Emb[sp*NSTATES + s], 0.f, 0.f};
        #pragma unroll
        for (int hh = 0; hh < HIDDEN; hh++) {
            float w = W2[hh*NSTATES + s];
            J hv = s_hid[at][hh];
            p.v = fmaf(hv.v, w, p.v);
            p.d = fmaf(hv.d, w, p.d);
            p.h = fmaf(hv.h, w, p.h);
        }
        s_p[at][s] = p;
    }
    __syncthreads();

    // Phase 6: T_s = sum over pairs of p_j * radial
    if (tid < PPC) {
        int jl = s_j[tid];
        J r = s_rad[tid];
        #pragma unroll
        for (int s = 0; s < NSTATES; s++) {
            J t = jmul(s_p[jl][s], r);
            s_term[tid][s][0] = t.v;
            s_term[tid][s][1] = t.d;
            s_term[tid][s][2] = t.h;
        }
    }
    __syncthreads();

    // deterministic reduction + output
    if (tid < NSTATES*3) {
        int s = tid / 3, comp = tid % 3;
        float acc = 0.f;
        for (int p = 0; p < PPC; p++) acc += s_term[p][s][comp];
        int outIdx = ((c*NATOMS + aLoc)*3 + mu)*NSTATES + s;
        if (comp == 1) g_B[outIdx] = acc;
        if (comp == 2) g_H[outIdx] = acc;
        if (comp == 0 && aLoc == 0 && mu == 0) g_T[c*NSTATES + s] = acc;
    }
}

// ---------------- kernel B: assemble kinetic term + scalar loss ----------------
__global__ void finalize_kernel(const float* __restrict__ pot,
                                const float* __restrict__ massrev,
                                const float* __restrict__ elevel,
                                float* __restrict__ out)
{
    __shared__ float red[NCONF*NSTATES];
    int t = threadIdx.x;
    if (t < NCONF*NSTATES) {
        int c = t / NSTATES, s = t % NSTATES;
        float T0 = g_T[c*NSTATES + 0];
        float Ts = g_T[c*NSTATES + s];
        float psi = (s == 0) ? T0*T0 : Ts;
        float kin = 0.f;
        for (int a = 0; a < NATOMS; a++) {
            float lap = 0.f;
            #pragma unroll
            for (int mu = 0; mu < 3; mu++) {
                int idx = ((c*NATOMS + a)*3 + mu)*NSTATES + s;
                float b  = g_B[idx];
                float h2 = g_H[idx];
                lap += (s == 0) ? (2.f*b*b + 2.f*T0*h2) : h2;
            }
            kin += massrev[c*NATOMS + a] * lap;
        }
        kin *= -0.5f;
        float pe  = pot[c] - pot[NCONF-1];
        float vib = (kin + psi*pe) / psi;
        float dv  = vib - elevel[s];
        red[t] = dv*dv;
    }
    __syncthreads();
    if (t == 0) {
        float acc = 0.f;
        for (int i = 0; i < NCONF*NSTATES; i++) acc += red[i];
        out[0] = acc;
    }
}

extern "C" void kernel_launch(void* const* d_in, const int* in_sizes, int n_in,
                              void* d_out, int out_size)
{
    // metadata order: eigen_weight, pot, cart, numatoms, species, massrev,
    //                 atom_index, shifts, W1, B1, W2, Emb, elevel
    const float* pot     = (const float*)d_in[1];
    const float* cart    = (const float*)d_in[2];
    const int*   species = (const int*)  d_in[4];
    const float* massrev = (const float*)d_in[5];
    const int*   ai      = (const int*)  d_in[6];
    const float* shifts  = (const float*)d_in[7];
    const float* W1      = (const float*)d_in[8];
    const float* B1      = (const float*)d_in[9];
    const float* W2      = (const float*)d_in[10];
    const float* Emb     = (const float*)d_in[11];
    const float* elevel  = (const float*)d_in[12];
    int npairs = in_sizes[6] / 2;

    wave_hess_kernel<<<NDIR, 128>>>(cart, species, ai, shifts, W1, B1, W2, Emb, npairs);
    finalize_kernel<<<1, 32>>>(pot, massrev, elevel, (float*)d_out);
}

// round 2
// speedup vs baseline: 1.0135x; 1.0135x over previous
#include <cuda_runtime.h>

#define NCONF   8
#define NATOMS  10
#define NSTATES 4
#define NBASIS  24
#define HIDDEN  48
#define PPC     (NATOMS*(NATOMS-1))   // 90 pairs per configuration
#define NDIRS   (NATOMS*3)            // 30 directions per config
#define NTHREADS 1024

#define PI_F    3.14159265358979323846f
#define CUT     6.0f
#define KARG    (PI_F/CUT)
#define ALPHA_F 1.5f
#define FULLM   0xffffffffu

// cross-block reduction scratch (no cudaMalloc allowed)
__device__ float g_partial[NCONF];
__device__ int   g_ctr = 0;

struct Sh {
    // pair geometry (value path)
    float dv[PPC][3];
    float dist[PPC];
    float radv[PPC], rad1[PPC], rad2[PPC];   // sin^3 radial jets wrt distance
    float fc0[PPC], fc1[PPC], fc2[PPC];      // cosine cutoff jets wrt distance
    int   pi[PPC], pj[PPC];
    int   qidx[NATOMS][NATOMS];              // pair index lookup (i,j)
    // per (pair,basis) rbf*fcut jets wrt distance
    float G0[PPC][NBASIS], G1[PPC][NBASIS], G2[PPC][NBASIS];
    // weights cached
    float W1s[NBASIS][HIDDEN];
    float W2s[HIDDEN][NSTATES];
    // value path through MLP
    float densv[NATOMS][NBASIS];
    float tval[NATOMS][HIDDEN];
    float f1[NATOMS][HIDDEN], f2[NATOMS][HIDDEN];
    float pv[NATOMS][NSTATES];
    // direction-independent linear-response precomputes
    float M1[NATOMS][NBASIS][NSTATES];       // W2^T (f1 . W1^T)
    float U1[PPC][HIDDEN];                   // G1 . W1
    float V1[PPC][NSTATES], V2[PPC][NSTATES], Qq[PPC][NSTATES];
    float R[NATOMS];                         // sum of radial over pairs grouped by neighbor
    float Tval[NSTATES];
    // per-warp (direction) scratch
    float wddc[NDIRS][9], wdhc[NDIRS][9];    // pairs with center == A
    float wddn[NDIRS][9], wdhn[NDIRS][9];    // pairs with neighbor == A
    int   wqc[NDIRS][9], wqn[NDIRS][9], wj[NDIRS][9];
    float wpd[NDIRS][NATOMS][NSTATES], wph[NDIRS][NATOMS][NSTATES];
    // per-direction outputs
    float Bsh[NDIRS][NSTATES], Hsh[NDIRS][NSTATES];
    float losspart[NSTATES];
};

__global__ void __launch_bounds__(NTHREADS, 1)
fused_kernel(const float* __restrict__ pot, const float* __restrict__ cart,
             const int* __restrict__ species, const float* __restrict__ massrev,
             const int* __restrict__ ai, const float* __restrict__ shifts,
             const float* __restrict__ W1, const float* __restrict__ B1,
             const float* __restrict__ W2, const float* __restrict__ Emb,
             const float* __restrict__ elevel, float* __restrict__ out,
             int npairs)
{
    extern __shared__ unsigned char smem_raw[];
    Sh& sh = *reinterpret_cast<Sh*>(smem_raw);

    const int tid = threadIdx.x;
    const int c   = blockIdx.x;

    // ---------------- Phase 0: cache weights ----------------
    for (int i = tid; i < NBASIS*HIDDEN; i += NTHREADS)
        sh.W1s[i / HIDDEN][i % HIDDEN] = W1[i];
    for (int i = tid; i < HIDDEN*NSTATES; i += NTHREADS)
        sh.W2s[i / NSTATES][i % NSTATES] = W2[i];

    // ---------------- Phase 1: pair geometry jets ----------------
    if (tid < PPC) {
        int pg = c*PPC + tid;
        int gi = ai[pg];
        int gj = ai[npairs + pg];
        int il = gi - c*NATOMS, jl = gj - c*NATOMS;
        sh.pi[tid] = il; sh.pj[tid] = jl;
        sh.qidx[il][jl] = tid;
        float d2 = 0.f;
        #pragma unroll
        for (int nu = 0; nu < 3; nu++) {
            float v = cart[gj*3+nu] + shifts[pg*3+nu] - cart[gi*3+nu];
            sh.dv[tid][nu] = v;
            d2 = fmaf(v, v, d2);
        }
        float d = sqrtf(d2);
        sh.dist[tid] = d;
        float arg = d * KARG;
        float sn = sinf(arg), cs = cosf(arg);
        sh.radv[tid] = sn*sn*sn;
        sh.rad1[tid] = 3.f*sn*sn*cs * KARG;
        sh.rad2[tid] = (6.f*sn*cs*cs - 3.f*sn*sn*sn) * (KARG*KARG);
        if (d < CUT) {
            sh.fc0[tid] = 0.5f*(cs + 1.f);
            sh.fc1[tid] = -0.5f*KARG*sn;
            sh.fc2[tid] = -0.5f*KARG*KARG*cs;
        } else {
            sh.fc0[tid] = 0.f; sh.fc1[tid] = 0.f; sh.fc2[tid] = 0.f;
        }
    }
    __syncthreads();

    // ---------------- Phase 2: rbf*fcut jets per (pair, basis) ----------------
    for (int it = tid; it < PPC*NBASIS; it += NTHREADS) {
        int p = it / NBASIS, b = it % NBASIS;
        float center = CUT * (float)b / (float)(NBASIS - 1);
        float t  = sh.dist[p] - center;
        float rb = expf(-ALPHA_F * t * t);
        float r1 = -2.f*ALPHA_F*t * rb;                       // -3t*rb
        float r2 = (4.f*ALPHA_F*ALPHA_F*t*t - 2.f*ALPHA_F)*rb; // (9t^2-3)*rb
        float f0 = sh.fc0[p], fd1 = sh.fc1[p], fd2 = sh.fc2[p];
        sh.G0[p][b] = rb*f0;
        sh.G1[p][b] = r1*f0 + rb*fd1;
        sh.G2[p][b] = r2*f0 + 2.f*r1*fd1 + rb*fd2;
    }
    __syncthreads();

    // ---------------- Phase 3: density values + R ----------------
    for (int it = tid; it < NATOMS*NBASIS; it += NTHREADS) {
        int at = it / NBASIS, b = it % NBASIS;
        float acc = 0.f;
        #pragma unroll
        for (int j = 0; j < NATOMS; j++)
            if (j != at) acc += sh.G0[sh.qidx[at][j]][b];
        sh.densv[at][b] = acc;
    }
    if (tid < NATOMS) {
        float r = 0.f;
        for (int p = 0; p < PPC; p++)
            if (sh.pj[p] == tid) r += sh.radv[p];
        sh.R[tid] = r;
    }
    __syncthreads();

    // ---------------- Phase 4: hidden-layer value path ----------------
    for (int it = tid; it < NATOMS*HIDDEN; it += NTHREADS) {
        int at = it / HIDDEN, hh = it % HIDDEN;
        int sp = species[c*NATOMS + at];
        float u = B1[sp*HIDDEN + hh];
        #pragma unroll
        for (int b = 0; b < NBASIS; b++)
            u = fmaf(sh.densv[at][b], sh.W1s[b][hh], u);
        float t  = tanhf(u);
        float f1 = 1.f - t*t;
        sh.tval[at][hh] = t;
        sh.f1[at][hh]   = f1;
        sh.f2[at][hh]   = -2.f*t*f1;
    }
    __syncthreads();

    // ---------------- Phase 5: M1, U1, pv ----------------
    for (int it = tid; it < NATOMS*NBASIS*NSTATES; it += NTHREADS) {
        int at = it / (NBASIS*NSTATES);
        int b  = (it / NSTATES) % NBASIS;
        int s  = it % NSTATES;
        float acc = 0.f;
        #pragma unroll
        for (int hh = 0; hh < HIDDEN; hh++)
            acc = fmaf(sh.W1s[b][hh]*sh.f1[at][hh], sh.W2s[hh][s], acc);
        sh.M1[at][b][s] = acc;
    }
    for (int it = tid; it < PPC*HIDDEN; it += NTHREADS) {
        int q = it / HIDDEN, hh = it % HIDDEN;
        float acc = 0.f;
        #pragma unroll
        for (int b = 0; b < NBASIS; b++)
            acc = fmaf(sh.G1[q][b], sh.W1s[b][hh], acc);
        sh.U1[q][hh] = acc;
    }
    for (int it = tid; it < NATOMS*NSTATES; it += NTHREADS) {
        int at = it / NSTATES, s = it % NSTATES;
        int sp = species[c*NATOMS + at];
        float acc = Emb[sp*NSTATES + s];
        #pragma unroll
        for (int hh = 0; hh < HIDDEN; hh++)
            acc = fmaf(sh.tval[at][hh], sh.W2s[hh][s], acc);
        sh.pv[at][s] = acc;
    }
    __syncthreads();

    // ---------------- Phase 6: V1, V2, Q, T values ----------------
    for (int it = tid; it < PPC*NSTATES; it += NTHREADS) {
        int q = it / NSTATES, s = it % NSTATES;
        int cen = sh.pi[q];
        float v1 = 0.f, v2 = 0.f, qq = 0.f;
        #pragma unroll
        for (int b = 0; b < NBASIS; b++) {
            float m = sh.M1[cen][b][s];
            v1 = fmaf(sh.G1[q][b], m, v1);
            v2 = fmaf(sh.G2[q][b], m, v2);
        }
        #pragma unroll
        for (int hh = 0; hh < HIDDEN; hh++) {
            float u = sh.U1[q][hh];
            qq = fmaf(sh.f2[cen][hh]*u*u, sh.W2s[hh][s], qq);
        }
        sh.V1[q][s] = v1; sh.V2[q][s] = v2; sh.Qq[q][s] = qq;
    }
    if (tid < NSTATES) {
        float acc = 0.f;
        #pragma unroll
        for (int j = 0; j < NATOMS; j++)
            acc = fmaf(sh.pv[j][tid], sh.R[j], acc);
        sh.Tval[tid] = acc;
    }
    __syncthreads();

    // ---------------- Direction phase: warp w -> direction (aLoc, mu) ----------------
    const int w    = tid >> 5;
    const int lane = tid & 31;
    if (w < NDIRS) {
        const int aLoc = w / 3;
        const int mu   = w % 3;

        // Step 1: jets of the 18 distances involving atom A
        if (lane < 9) {
            int j  = lane + (lane >= aLoc ? 1 : 0);
            int qc = sh.qidx[aLoc][j];   // center A  (i == A) -> dd = -dv[mu]/d
            int qn = sh.qidx[j][aLoc];   // neighbor A (j == A) -> dd = +dv[mu]/d
            float invc = 1.f / sh.dist[qc];
            float ec = sh.dv[qc][mu] * invc;
            sh.wddc[w][lane] = -ec;
            sh.wdhc[w][lane] = (1.f - ec*ec) * invc;
            float invn = 1.f / sh.dist[qn];
            float en = sh.dv[qn][mu] * invn;
            sh.wddn[w][lane] = en;
            sh.wdhn[w][lane] = (1.f - en*en) * invn;
            sh.wqc[w][lane] = qc; sh.wqn[w][lane] = qn; sh.wj[w][lane] = j;
        }
        __syncwarp();

        // Step 2: perturbed atom A -- full linear response + quadratic tanh term
        float q0 = 0.f, q1 = 0.f, q2 = 0.f, q3 = 0.f;
        #pragma unroll
        for (int rep = 0; rep < 2; rep++) {
            int hh = lane + rep*32;
            if (hh < HIDDEN) {
                float ud = 0.f;
                #pragma unroll
                for (int k = 0; k < 9; k++)
                    ud = fmaf(sh.wddc[w][k], sh.U1[sh.wqc[w][k]][hh], ud);
                float cf = sh.f2[aLoc][hh] * ud * ud;
                q0 = fmaf(cf, sh.W2s[hh][0], q0);
                q1 = fmaf(cf, sh.W2s[hh][1], q1);
                q2 = fmaf(cf, sh.W2s[hh][2], q2);
                q3 = fmaf(cf, sh.W2s[hh][3], q3);
            }
        }
        #pragma unroll
        for (int off = 16; off > 0; off >>= 1) {
            q0 += __shfl_xor_sync(FULLM, q0, off);
            q1 += __shfl_xor_sync(FULLM, q1, off);
            q2 += __shfl_xor_sync(FULLM, q2, off);
            q3 += __shfl_xor_sync(FULLM, q3, off);
        }
        float accA = 0.f;
        if (lane < 8) {
            int s = lane & 3;
            bool second = lane >= 4;   // lanes 4-7: linear 2nd-order; 0-3: 1st-order
            #pragma unroll
            for (int k = 0; k < 9; k++) {
                int qp = sh.wqc[w][k];
                float dd = sh.wddc[w][k], dh = sh.wdhc[w][k];
                accA += second ? fmaf(dd*dd, sh.V2[qp][s], dh*sh.V1[qp][s])
                               : dd*sh.V1[qp][s];
            }
        }
        {
            float qsel = ((lane & 3) == 0) ? q0 : ((lane & 3) == 1) ? q1
                        : ((lane & 3) == 2) ? q2 : q3;
            if (lane < 4)       sh.wpd[w][aLoc][lane]   = accA;
            else if (lane < 8)  sh.wph[w][aLoc][lane-4] = accA + qsel;
        }
        __syncwarp();

        // Step 3: the 9 other atoms (single contributing pair each)
        #pragma unroll
        for (int base = 0; base < 36; base += 32) {
            int item = base + lane;
            if (item < 36) {
                int k = item >> 2, s = item & 3;
                int qp = sh.wqn[w][k];
                float dd = sh.wddn[w][k], dh = sh.wdhn[w][k];
                float pd = dd * sh.V1[qp][s];
                float ph = dd*dd*(sh.V2[qp][s] + sh.Qq[qp][s]) + dh*sh.V1[qp][s];
                int at = sh.wj[w][k];
                sh.wpd[w][at][s] = pd;
                sh.wph[w][at][s] = ph;
            }
        }
        __syncwarp();

        // Step 4: assemble T' and T'' for this direction
        {
            int s = lane & 3, g = lane >> 2;   // g in 0..7
            float td = 0.f, th = 0.f;
            for (int k = g; k < 9; k += 8) {
                int qc = sh.wqc[w][k], qn = sh.wqn[w][k], j = sh.wj[w][k];
                float ddc = sh.wddc[w][k], dhc = sh.wdhc[w][k];
                float rdc = sh.rad1[qc]*ddc;
                float rhc = fmaf(sh.rad2[qc], ddc*ddc, sh.rad1[qc]*dhc);
                td = fmaf(sh.pv[j][s], rdc, td);
                th = fmaf(2.f*sh.wpd[w][j][s], rdc, fmaf(sh.pv[j][s], rhc, th));
                float ddn = sh.wddn[w][k], dhn = sh.wdhn[w][k];
                float rdn = sh.rad1[qn]*ddn;
                float rhn = fmaf(sh.rad2[qn], ddn*ddn, sh.rad1[qn]*dhn);
                td = fmaf(sh.pv[aLoc][s], rdn, td);
                th = fmaf(2.f*sh.wpd[w][aLoc][s], rdn, fmaf(sh.pv[aLoc][s], rhn, th));
            }
            for (int at = g; at < NATOMS; at += 8) {
                td = fmaf(sh.wpd[w][at][s], sh.R[at], td);
                th = fmaf(sh.wph[w][at][s], sh.R[at], th);
            }
            #pragma unroll
            for (int off = 4; off < 32; off <<= 1) {
                td += __shfl_xor_sync(FULLM, td, off);
                th += __shfl_xor_sync(FULLM, th, off);
            }
            if (lane < 4) {
                sh.Bsh[w][lane] = td;
                sh.Hsh[w][lane] = th;
            }
        }
    }
    __syncthreads();

    // ---------------- Finalize: per-config loss, then last-block total ----------------
    if (tid < NSTATES) {
        int s = tid;
        float T0 = sh.Tval[0];
        float kin = 0.f;
        for (int d = 0; d < NDIRS; d++) {
            int a = d / 3;
            float Bv = sh.Bsh[d][s], Hv = sh.Hsh[d][s];
            float lap = (s == 0) ? (2.f*Bv*Bv + 2.f*T0*Hv) : Hv;
            kin = fmaf(massrev[c*NATOMS + a], lap, kin);
        }
        kin *= -0.5f;
        float psi = (s == 0) ? T0*T0 : sh.Tval[s];
        float pe  = pot[c] - pot[NCONF-1];
        float vib = (kin + psi*pe) / psi;
        float dvv = vib - elevel[s];
        sh.losspart[s] = dvv*dvv;
    }
    __syncthreads();
    if (tid == 0) {
        g_partial[c] = sh.losspart[0] + sh.losspart[1] + sh.losspart[2] + sh.losspart[3];
        __threadfence();
        if (atomicAdd(&g_ctr, 1) == NCONF - 1) {
            volatile float* gp = g_partial;
            float acc = 0.f;
            #pragma unroll
            for (int c2 = 0; c2 < NCONF; c2++) acc += gp[c2];
            out[0] = acc;
            g_ctr = 0;   // reset for next (graph-replayed) launch
        }
    }
}

extern "C" void kernel_launch(void* const* d_in, const int* in_sizes, int n_in,
                              void* d_out, int out_size)
{
    // metadata order: eigen_weight, pot, cart, numatoms, species, massrev,
    //                 atom_index, shifts, W1, B1, W2, Emb, elevel
    const float* pot     = (const float*)d_in[1];
    const float* cart    = (const float*)d_in[2];
    const int*   species = (const int*)  d_in[4];
    const float* massrev = (const float*)d_in[5];
    const int*   ai      = (const int*)  d_in[6];
    const float* shifts  = (const float*)d_in[7];
    const float* W1      = (const float*)d_in[8];
    const float* B1      = (const float*)d_in[9];
    const float* W2      = (const float*)d_in[10];
    const float* Emb     = (const float*)d_in[11];
    const float* elevel  = (const float*)d_in[12];
    int npairs = in_sizes[6] / 2;

    static bool attr_set = false;
    if (!attr_set) {
        cudaFuncSetAttribute(fused_kernel,
                             cudaFuncAttributeMaxDynamicSharedMemorySize,
                             (int)sizeof(Sh));
        attr_set = true;
    }

    fused_kernel<<<NCONF, NTHREADS, sizeof(Sh)>>>(
        pot, cart, species, massrev, ai, shifts,
        W1, B1, W2, Emb, elevel, (float*)d_out, npairs);
}

// round 4
// speedup vs baseline: 1.2453x; 1.2287x over previous
#include <cuda_runtime.h>

#define NCONF   8
#define NATOMS  10
#define NSTATES 4
#define NBASIS  24
#define HIDDEN  48
#define PPC     90            // ordered pairs per config
#define NT      256
#define NBLOCKS (NCONF*NATOMS)

#define PI_F    3.14159265358979323846f
#define CUT     6.0f
#define KARG    (PI_F/CUT)
#define AL      1.5f
#define FULLM   0xffffffffu

// cross-block scratch (no cudaMalloc allowed)
__device__ float g_kin[NCONF*NATOMS*NSTATES];
__device__ float g_T[NCONF*NSTATES];
__device__ int   g_ctr = 0;

__global__ void __launch_bounds__(NT, 1)
fused_kernel(const float* __restrict__ pot, const float* __restrict__ cart,
             const int* __restrict__ species, const float* __restrict__ massrev,
             const int* __restrict__ ai, const float* __restrict__ shifts,
             const float* __restrict__ W1, const float* __restrict__ B1,
             const float* __restrict__ W2, const float* __restrict__ Emb,
             const float* __restrict__ elevel, float* __restrict__ out,
             int npairs)
{
    __shared__ float dvs[PPC][3], dist[PPC];
    __shared__ float radv[PPC], rad1[PPC], rad2[PPC];
    __shared__ float fc0[PPC], fc1[PPC], fc2[PPC];
    __shared__ int   qidx[NATOMS][NATOMS], pjj[PPC];
    __shared__ float G0[PPC][NBASIS];
    __shared__ __align__(16) float W1s[NBASIS][HIDDEN];
    __shared__ __align__(16) float W2s[HIDDEN][NSTATES];
    __shared__ float densv[NATOMS][NBASIS];
    __shared__ float tval[NATOMS][HIDDEN], f1a[NATOMS][HIDDEN], f2a[NATOMS][HIDDEN];
    __shared__ float pv[NATOMS][NSTATES];
    __shared__ float Rr[NATOMS], Tval[NSTATES];
    __shared__ int   jlist[9], qcp[9], qnp[9];
    __shared__ float G1k[18][NBASIS], G2k[18][NBASIS];
    __shared__ __align__(16) float U1[18][HIDDEN];
    __shared__ __align__(16) float U2[18][HIDDEN];
    __shared__ float V1[18][NSTATES], V2[18][NSTATES], Qn[9][NSTATES];
    __shared__ float wdd[3][18], wdh[3][18];
    __shared__ float wpd[3][NATOMS][NSTATES], wph[3][NATOMS][NSTATES];
    __shared__ float Bsh[3][NSTATES], Hsh[3][NSTATES];
    __shared__ int   isLast;

    const int tid = threadIdx.x;
    const int c   = blockIdx.x / NATOMS;
    const int A   = blockIdx.x % NATOMS;

    // -------- P1: weights + pair geometry --------
    for (int i = tid; i < NBASIS*HIDDEN; i += NT) ((float*)W1s)[i] = W1[i];
    for (int i = tid; i < HIDDEN*NSTATES; i += NT) ((float*)W2s)[i] = W2[i];
    if (tid < PPC) {
        int pg = c*PPC + tid;
        int gi = ai[pg];
        int gj = ai[npairs + pg];
        int il = gi - c*NATOMS, jl = gj - c*NATOMS;
        pjj[tid] = jl;
        qidx[il][jl] = tid;
        float d2 = 0.f;
        #pragma unroll
        for (int nu = 0; nu < 3; nu++) {
            float v = cart[gj*3+nu] + shifts[pg*3+nu] - cart[gi*3+nu];
            dvs[tid][nu] = v;
            d2 = fmaf(v, v, d2);
        }
        float d = sqrtf(d2);
        dist[tid] = d;
        float arg = d * KARG;
        float sn = sinf(arg), cs = cosf(arg);
        radv[tid] = sn*sn*sn;
        rad1[tid] = 3.f*sn*sn*cs * KARG;
        rad2[tid] = (6.f*sn*cs*cs - 3.f*sn*sn*sn) * (KARG*KARG);
        if (d < CUT) {
            fc0[tid] = 0.5f*(cs + 1.f);
            fc1[tid] = -0.5f*KARG*sn;
            fc2[tid] = -0.5f*KARG*KARG*cs;
        } else {
            fc0[tid] = 0.f; fc1[tid] = 0.f; fc2[tid] = 0.f;
        }
    }
    __syncthreads();

    // -------- P2a: A-pair lists, R, G0 for all pairs --------
    if (tid < 9) {
        int j = tid + (tid >= A ? 1 : 0);
        jlist[tid] = j;
        qcp[tid] = qidx[A][j];
        qnp[tid] = qidx[j][A];
    } else if (tid >= 32 && tid < 32 + NATOMS) {
        int at = tid - 32;
        float r = 0.f;
        for (int p = 0; p < PPC; p++)
            if (pjj[p] == at) r += radv[p];
        Rr[at] = r;
    }
    for (int it = tid; it < PPC*NBASIS; it += NT) {
        int p = it / NBASIS, b = it % NBASIS;
        float center = CUT * (float)b / (float)(NBASIS - 1);
        float t = dist[p] - center;
        G0[p][b] = expf(-AL*t*t) * fc0[p];
    }
    __syncthreads();

    // -------- P2b: G1/G2 jets on the 18 A-pairs + density values --------
    for (int it = tid; it < 18*NBASIS; it += NT) {
        int k = it / NBASIS, b = it % NBASIS;
        int qp = (k < 9) ? qcp[k] : qnp[k-9];
        float center = CUT * (float)b / (float)(NBASIS - 1);
        float t  = dist[qp] - center;
        float rb = expf(-AL*t*t);
        float r1 = -2.f*AL*t * rb;
        float r2 = (4.f*AL*AL*t*t - 2.f*AL)*rb;
        float f0 = fc0[qp], fd1 = fc1[qp], fd2 = fc2[qp];
        G1k[k][b] = r1*f0 + rb*fd1;
        G2k[k][b] = r2*f0 + 2.f*r1*fd1 + rb*fd2;
    }
    for (int it = tid; it < NATOMS*NBASIS; it += NT) {
        int at = it / NBASIS, b = it % NBASIS;
        float acc = 0.f;
        #pragma unroll
        for (int j = 0; j < NATOMS; j++)
            if (j != at) acc += G0[qidx[at][j]][b];
        densv[at][b] = acc;
    }
    __syncthreads();

    // -------- P3: tanh value path + U1/U2 + direction distance jets --------
    for (int it = tid; it < NATOMS*HIDDEN; it += NT) {
        int at = it / HIDDEN, hh = it % HIDDEN;
        int sp = species[c*NATOMS + at];
        float u = B1[sp*HIDDEN + hh];
        #pragma unroll
        for (int b = 0; b < NBASIS; b++)
            u = fmaf(densv[at][b], W1s[b][hh], u);
        float t  = tanhf(u);
        float f1 = 1.f - t*t;
        tval[at][hh] = t;
        f1a[at][hh]  = f1;
        f2a[at][hh]  = -2.f*t*f1;
    }
    if (tid < 18*12) {   // U1/U2, hh quad-blocked
        int k = tid / 12, hq = (tid % 12) * 4;
        float a0=0,a1=0,a2=0,a3=0,b0=0,b1=0,b2=0,b3=0;
        #pragma unroll
        for (int b = 0; b < NBASIS; b++) {
            float g1 = G1k[k][b], g2 = G2k[k][b];
            float4 w = *(const float4*)&W1s[b][hq];
            a0 = fmaf(g1, w.x, a0); a1 = fmaf(g1, w.y, a1);
            a2 = fmaf(g1, w.z, a2); a3 = fmaf(g1, w.w, a3);
            b0 = fmaf(g2, w.x, b0); b1 = fmaf(g2, w.y, b1);
            b2 = fmaf(g2, w.z, b2); b3 = fmaf(g2, w.w, b3);
        }
        U1[k][hq]=a0; U1[k][hq+1]=a1; U1[k][hq+2]=a2; U1[k][hq+3]=a3;
        U2[k][hq]=b0; U2[k][hq+1]=b1; U2[k][hq+2]=b2; U2[k][hq+3]=b3;
    }
    if (tid >= 224) {  // wdd/wdh: 3 mu x 18 pairs = 54 items on 32 threads (2 iters)
        for (int it = tid - 224; it < 54; it += 32) {
            int mu = it / 18, k = it % 18;
            int qp = (k < 9) ? qcp[k] : qnp[k-9];
            float inv = 1.f / dist[qp];
            float e = dvs[qp][mu] * inv;
            wdd[mu][k] = (k < 9) ? -e : e;
            wdh[mu][k] = (1.f - e*e) * inv;
        }
    }
    __syncthreads();

    // -------- P4: pv, V1/V2, Qn --------
    if (tid < NATOMS*NSTATES) {
        int at = tid >> 2, s = tid & 3;
        int sp = species[c*NATOMS + at];
        float acc = Emb[sp*NSTATES + s];
        #pragma unroll
        for (int hh = 0; hh < HIDDEN; hh++)
            acc = fmaf(tval[at][hh], W2s[hh][s], acc);
        pv[at][s] = acc;
    } else if (tid >= 64 && tid < 64+18) {
        int k = tid - 64;
        int cen = (k < 9) ? A : jlist[k-9];
        float v10=0,v11=0,v12=0,v13=0, v20=0,v21=0,v22=0,v23=0;
        #pragma unroll
        for (int hh = 0; hh < HIDDEN; hh++) {
            float u1 = U1[k][hh] * f1a[cen][hh];
            float u2 = U2[k][hh] * f1a[cen][hh];
            float4 w = *(const float4*)&W2s[hh][0];
            v10 = fmaf(u1, w.x, v10); v11 = fmaf(u1, w.y, v11);
            v12 = fmaf(u1, w.z, v12); v13 = fmaf(u1, w.w, v13);
            v20 = fmaf(u2, w.x, v20); v21 = fmaf(u2, w.y, v21);
            v22 = fmaf(u2, w.z, v22); v23 = fmaf(u2, w.w, v23);
        }
        V1[k][0]=v10; V1[k][1]=v11; V1[k][2]=v12; V1[k][3]=v13;
        V2[k][0]=v20; V2[k][1]=v21; V2[k][2]=v22; V2[k][3]=v23;
    } else if (tid >= 96 && tid < 96+9) {
        int k9 = tid - 96;
        int cen = jlist[k9];
        float q0=0,q1=0,q2=0,q3=0;
        #pragma unroll
        for (int hh = 0; hh < HIDDEN; hh++) {
            float u = U1[9+k9][hh];
            float cf = f2a[cen][hh] * u * u;
            float4 w = *(const float4*)&W2s[hh][0];
            q0 = fmaf(cf, w.x, q0); q1 = fmaf(cf, w.y, q1);
            q2 = fmaf(cf, w.z, q2); q3 = fmaf(cf, w.w, q3);
        }
        Qn[k9][0]=q0; Qn[k9][1]=q1; Qn[k9][2]=q2; Qn[k9][3]=q3;
    }
    __syncthreads();

    // -------- P5: per-direction (mu = warp 0..2) + Tval (tid 96..99) --------
    const int w    = tid >> 5;
    const int lane = tid & 31;
    if (tid >= 96 && tid < 96+NSTATES) {
        int s = tid - 96;
        float acc = 0.f;
        #pragma unroll
        for (int j = 0; j < NATOMS; j++)
            acc = fmaf(pv[j][s], Rr[j], acc);
        Tval[s] = acc;
    }
    if (w < 3) {
        const int mu = w;
        // Step 2: perturbed atom A — quadratic tanh cross term + linear response
        float q0=0,q1=0,q2=0,q3=0;
        #pragma unroll
        for (int rep = 0; rep < 2; rep++) {
            int hh = lane + rep*32;
            if (hh < HIDDEN) {
                float ud = 0.f;
                #pragma unroll
                for (int k = 0; k < 9; k++)
                    ud = fmaf(wdd[mu][k], U1[k][hh], ud);
                float cf = f2a[A][hh] * ud * ud;
                q0 = fmaf(cf, W2s[hh][0], q0);
                q1 = fmaf(cf, W2s[hh][1], q1);
                q2 = fmaf(cf, W2s[hh][2], q2);
                q3 = fmaf(cf, W2s[hh][3], q3);
            }
        }
        #pragma unroll
        for (int off = 16; off > 0; off >>= 1) {
            q0 += __shfl_xor_sync(FULLM, q0, off);
            q1 += __shfl_xor_sync(FULLM, q1, off);
            q2 += __shfl_xor_sync(FULLM, q2, off);
            q3 += __shfl_xor_sync(FULLM, q3, off);
        }
        float accA = 0.f;
        if (lane < 8) {
            int s = lane & 3;
            bool second = lane >= 4;
            #pragma unroll
            for (int k = 0; k < 9; k++) {
                float dd = wdd[mu][k], dh = wdh[mu][k];
                accA += second ? fmaf(dd*dd, V2[k][s], dh*V1[k][s])
                               : dd*V1[k][s];
            }
        }
        {
            float qsel = ((lane & 3)==0) ? q0 : ((lane & 3)==1) ? q1
                        : ((lane & 3)==2) ? q2 : q3;
            if (lane < 4)      wpd[mu][A][lane]   = accA;
            else if (lane < 8) wph[mu][A][lane-4] = accA + qsel;
        }
        __syncwarp();

        // Step 3: the 9 neighbor atoms (single perturbed pair each)
        #pragma unroll
        for (int base = 0; base < 36; base += 32) {
            int item = base + lane;
            if (item < 36) {
                int k9 = item >> 2, s = item & 3;
                int kk = 9 + k9;
                float dd = wdd[mu][kk], dh = wdh[mu][kk];
                float pd = dd * V1[kk][s];
                float ph = dd*dd*(V2[kk][s] + Qn[k9][s]) + dh*V1[kk][s];
                int at = jlist[k9];
                wpd[mu][at][s] = pd;
                wph[mu][at][s] = ph;
            }
        }
        __syncwarp();

        // Step 4: assemble T' and T''
        {
            int s = lane & 3, g = lane >> 2;
            float td = 0.f, th = 0.f;
            for (int k = g; k < 9; k += 8) {
                int qc = qcp[k], qn = qnp[k], j = jlist[k];
                float ddc = wdd[mu][k], dhc = wdh[mu][k];
                float rdc = rad1[qc]*ddc;
                float rhc = fmaf(rad2[qc], ddc*ddc, rad1[qc]*dhc);
                td = fmaf(pv[j][s], rdc, td);
                th = fmaf(2.f*wpd[mu][j][s], rdc, fmaf(pv[j][s], rhc, th));
                float ddn = wdd[mu][9+k], dhn = wdh[mu][9+k];
                float rdn = rad1[qn]*ddn;
                float rhn = fmaf(rad2[qn], ddn*ddn, rad1[qn]*dhn);
                td = fmaf(pv[A][s], rdn, td);
                th = fmaf(2.f*wpd[mu][A][s], rdn, fmaf(pv[A][s], rhn, th));
            }
            for (int at = g; at < NATOMS; at += 8) {
                td = fmaf(wpd[mu][at][s], Rr[at], td);
                th = fmaf(wph[mu][at][s], Rr[at], th);
            }
            #pragma unroll
            for (int off = 4; off < 32; off <<= 1) {
                td += __shfl_xor_sync(FULLM, td, off);
                th += __shfl_xor_sync(FULLM, th, off);
            }
            if (lane < 4) {
                Bsh[mu][lane] = td;
                Hsh[mu][lane] = th;
            }
        }
    }
    __syncthreads();

    // -------- P6: per-block kin partial + last-block finalize --------
    if (tid < NSTATES) {
        int s = tid;
        float T0 = Tval[0];
        float acc = 0.f;
        #pragma unroll
        for (int mu = 0; mu < 3; mu++) {
            float Bv = Bsh[mu][s], Hv = Hsh[mu][s];
            float lap = (s == 0) ? (2.f*Bv*Bv + 2.f*T0*Hv) : Hv;
            acc += lap;
        }
        g_kin[(c*NATOMS + A)*NSTATES + s] = massrev[c*NATOMS + A] * acc;
        if (A == 0) g_T[c*NSTATES + s] = Tval[s];
    }
    __syncthreads();
    if (tid == 0) {
        __threadfence();
        isLast = (atomicAdd(&g_ctr, 1) == NBLOCKS - 1);
    }
    __syncthreads();
    if (isLast && tid < 32) {
        __threadfence();
        int cc = tid >> 2, s = tid & 3;
        volatile float* gk = g_kin;
        volatile float* gt = g_T;
        float kin = 0.f;
        #pragma unroll
        for (int a = 0; a < NATOMS; a++)
            kin += gk[(cc*NATOMS + a)*NSTATES + s];
        kin *= -0.5f;
        float T0 = gt[cc*NSTATES + 0];
        float Ts = gt[cc*NSTATES + s];
        float psi = (s == 0) ? T0*T0 : Ts;
        float pe  = pot[cc] - pot[NCONF-1];
        float vib = (kin + psi*pe) / psi;
        float dvv = vib - elevel[s];
        float l = dvv*dvv;
        #pragma unroll
        for (int off = 16; off > 0; off >>= 1)
            l += __shfl_xor_sync(FULLM, l, off);
        if (tid == 0) {
            out[0] = l;
            g_ctr = 0;   // reset for next graph replay
        }
    }
}

extern "C" void kernel_launch(void* const* d_in, const int* in_sizes, int n_in,
                              void* d_out, int out_size)
{
    // metadata order: eigen_weight, pot, cart, numatoms, species, massrev,
    //                 atom_index, shifts, W1, B1, W2, Emb, elevel
    const float* pot     = (const float*)d_in[1];
    const float* cart    = (const float*)d_in[2];
    const int*   species = (const int*)  d_in[4];
    const float* massrev = (const float*)d_in[5];
    const int*   ai      = (const int*)  d_in[6];
    const float* shifts  = (const float*)d_in[7];
    const float* W1      = (const float*)d_in[8];
    const float* B1      = (const float*)d_in[9];
    const float* W2      = (const float*)d_in[10];
    const float* Emb     = (const float*)d_in[11];
    const float* elevel  = (const float*)d_in[12];
    int npairs = in_sizes[6] / 2;

    fused_kernel<<<NBLOCKS, NT>>>(pot, cart, species, massrev, ai, shifts,
                                  W1, B1, W2, Emb, elevel, (float*)d_out, npairs);
}

// round 5
// speedup vs baseline: 1.2909x; 1.0366x over previous
#include <cuda_runtime.h>

#define NCONF   8
#define NATOMS  10
#define NSTATES 4
#define NBASIS  24
#define HIDDEN  48
#define PPC     90            // ordered pairs per config (contiguous: p = i*9 + (j - (j>i)))
#define NT      256
#define NBLOCKS (NCONF*NATOMS)

#define PI_F 3.14159265358979323846f
#define CUT  6.0f
#define KARG (PI_F/CUT)
#define AL   1.5f
#define DLT  (CUT/23.0f)      // basis center spacing
#define FULLM 0xffffffffu

// cross-block scratch (no cudaMalloc allowed)
__device__ float g_kin[NCONF*NATOMS*NSTATES];
__device__ float g_T[NCONF*NSTATES];
__device__ float g_part[NCONF];
__device__ int   g_cfg[NCONF];
__device__ int   g_fin;

__device__ __forceinline__ int jlA(int t, int A) { return t + (t >= A); }

__global__ void __launch_bounds__(NT, 1)
fused_kernel(const float* __restrict__ pot, const float* __restrict__ cart,
             const int* __restrict__ species, const float* __restrict__ massrev,
             const float* __restrict__ W1, const float* __restrict__ B1,
             const float* __restrict__ W2, const float* __restrict__ Emb,
             const float* __restrict__ elevel, float* __restrict__ out)
{
    __shared__ float s_cart[NATOMS*3];
    __shared__ __align__(16) float W1s[NBASIS][52];
    __shared__ __align__(16) float W2s[HIDDEN][4];
    __shared__ float B1s[NATOMS][49];
    __shared__ float EmbA[NATOMS][4];
    __shared__ float s_pe, s_mass, s_el[4];
    __shared__ float G0[PPC][25];
    __shared__ float radv[PPC];
    __shared__ float G1k[18][25], G2k[18][25];
    __shared__ float rad1k[18], rad2k[18];
    __shared__ float wdd[3][18], wdh[3][18];
    __shared__ float densv[NATOMS][25];
    __shared__ float Rr[NATOMS];
    __shared__ float tval[NATOMS][49], f1a[NATOMS][49], f2a[NATOMS][49];
    __shared__ __align__(16) float U1[18][52], U2[18][52];
    __shared__ float pv[NATOMS][4];
    __shared__ float V1[18][4], V2[18][4], Qn[9][4];
    __shared__ float wpd[3][NATOMS][4], wph[3][NATOMS][4];
    __shared__ float Tval[4];
    __shared__ float Bsh[3][4], Hsh[3][4];

    const int tid = threadIdx.x;
    const int c   = blockIdx.x / NATOMS;
    const int A   = blockIdx.x % NATOMS;

    // -------- P1: all global loads up front --------
    for (int i = tid; i < NBASIS*HIDDEN; i += NT)
        W1s[i / HIDDEN][i % HIDDEN] = W1[i];
    if (tid < HIDDEN*NSTATES)
        W2s[tid >> 2][tid & 3] = W2[tid];
    for (int it = tid; it < NATOMS*HIDDEN; it += NT) {
        int at = it / HIDDEN, hh = it % HIDDEN;
        int sp = species[c*NATOMS + at];
        B1s[at][hh] = B1[sp*HIDDEN + hh];
    }
    if (tid < NATOMS*NSTATES) {
        int at = tid >> 2, s = tid & 3;
        int sp = species[c*NATOMS + at];
        EmbA[at][s] = Emb[sp*NSTATES + s];
    } else if (tid >= 64 && tid < 64 + NATOMS*3) {
        s_cart[tid - 64] = cart[c*NATOMS*3 + (tid - 64)];
    } else if (tid == 94) {
        s_mass = massrev[c*NATOMS + A];
    } else if (tid == 95) {
        s_pe = pot[c] - pot[NCONF-1];
    } else if (tid >= 96 && tid < 96 + NSTATES) {
        s_el[tid - 96] = elevel[tid - 96];
    }
    __syncthreads();

    // -------- P2: per-pair geometry + rbf recurrence (2 expf/pair) --------
    if (tid < PPC) {
        const int p = tid;
        const int i = p / 9, jr = p % 9;
        const int j = jr + (jr >= i);
        float dx = s_cart[j*3+0] - s_cart[i*3+0];
        float dy = s_cart[j*3+1] - s_cart[i*3+1];
        float dz = s_cart[j*3+2] - s_cart[i*3+2];
        float d2 = fmaf(dx, dx, fmaf(dy, dy, dz*dz));
        float d  = sqrtf(d2);
        float arg = d * KARG;
        float sn = sinf(arg), cs = cosf(arg);
        radv[p] = sn*sn*sn;
        float f0, fd1, fd2;
        if (d < CUT) {
            f0  = 0.5f*(cs + 1.f);
            fd1 = -0.5f*KARG*sn;
            fd2 = -0.5f*KARG*KARG*cs;
        } else { f0 = 0.f; fd1 = 0.f; fd2 = 0.f; }

        // rbf(b) = exp(-AL*(d - b*DLT)^2) via geometric recurrence
        const float gg = expf(-2.f*AL*DLT*DLT);
        float rb = expf(-AL*d2);
        float tc = expf(2.f*AL*DLT*d - AL*DLT*DLT);
        #pragma unroll
        for (int b = 0; b < NBASIS; b++) {
            G0[p][b] = rb * f0;
            rb *= tc; tc *= gg;
        }

        const bool isC = (i == A), isN = (j == A);
        if (isC || isN) {
            const int k = isC ? (j - (j > A)) : (9 + (i - (i > A)));
            rad1k[k] = 3.f*sn*sn*cs * KARG;
            rad2k[k] = (6.f*sn*cs*cs - 3.f*sn*sn*sn) * (KARG*KARG);
            float invd = 1.f / d;
            float sgn = isC ? -1.f : 1.f;
            float ex = dx*invd, ey = dy*invd, ez = dz*invd;
            wdd[0][k] = sgn*ex; wdh[0][k] = (1.f - ex*ex)*invd;
            wdd[1][k] = sgn*ey; wdh[1][k] = (1.f - ey*ey)*invd;
            wdd[2][k] = sgn*ez; wdh[2][k] = (1.f - ez*ez)*invd;
            // G1/G2 jets from a second recurrence pass
            float rb2 = expf(-AL*d2);
            float tc2 = expf(2.f*AL*DLT*d - AL*DLT*DLT);
            #pragma unroll
            for (int b = 0; b < NBASIS; b++) {
                float t  = d - (float)b*DLT;
                float r1 = -2.f*AL*t*rb2;
                float r2 = (4.f*AL*AL*t*t - 2.f*AL)*rb2;
                G1k[k][b] = r1*f0 + rb2*fd1;
                G2k[k][b] = r2*f0 + 2.f*r1*fd1 + rb2*fd2;
                rb2 *= tc2; tc2 *= gg;
            }
        }
    }
    __syncthreads();

    // -------- P3: densv (contiguous 9-sum), Rr, U1/U2 --------
    for (int it = tid; it < NATOMS*NBASIS + NATOMS; it += NT) {
        if (it < NATOMS*NBASIS) {
            int at = it / NBASIS, b = it % NBASIS;
            float acc = 0.f;
            #pragma unroll
            for (int r = 0; r < 9; r++) acc += G0[at*9 + r][b];
            densv[at][b] = acc;
        } else {
            int at = it - NATOMS*NBASIS;
            float r = 0.f;
            #pragma unroll
            for (int j = 0; j < NATOMS; j++) {
                if (j != at) r += radv[j*9 + (at - (at > j))];
            }
            Rr[at] = r;
        }
    }
    if (tid < 18*12) {   // U1/U2, hh quad-blocked
        int k = tid / 12, hq = (tid % 12) * 4;
        float a0=0,a1=0,a2=0,a3=0,b0=0,b1=0,b2=0,b3=0;
        #pragma unroll
        for (int b = 0; b < NBASIS; b++) {
            float g1 = G1k[k][b], g2 = G2k[k][b];
            float4 w = *(const float4*)&W1s[b][hq];
            a0 = fmaf(g1, w.x, a0); a1 = fmaf(g1, w.y, a1);
            a2 = fmaf(g1, w.z, a2); a3 = fmaf(g1, w.w, a3);
            b0 = fmaf(g2, w.x, b0); b1 = fmaf(g2, w.y, b1);
            b2 = fmaf(g2, w.z, b2); b3 = fmaf(g2, w.w, b3);
        }
        U1[k][hq]=a0; U1[k][hq+1]=a1; U1[k][hq+2]=a2; U1[k][hq+3]=a3;
        U2[k][hq]=b0; U2[k][hq+1]=b1; U2[k][hq+2]=b2; U2[k][hq+3]=b3;
    }
    __syncthreads();

    // -------- P4: tanh value path --------
    for (int it = tid; it < NATOMS*HIDDEN; it += NT) {
        int at = it / HIDDEN, hh = it % HIDDEN;
        float u = B1s[at][hh];
        #pragma unroll
        for (int b = 0; b < NBASIS; b++)
            u = fmaf(densv[at][b], W1s[b][hh], u);
        float t  = tanhf(u);
        float f1 = 1.f - t*t;
        tval[at][hh] = t;
        f1a[at][hh]  = f1;
        f2a[at][hh]  = -2.f*t*f1;
    }
    __syncthreads();

    // -------- P5: pv, V1/V2, Qn --------
    if (tid < NATOMS*NSTATES) {
        int at = tid >> 2, s = tid & 3;
        float acc = EmbA[at][s];
        #pragma unroll
        for (int hh = 0; hh < HIDDEN; hh++)
            acc = fmaf(tval[at][hh], W2s[hh][s], acc);
        pv[at][s] = acc;
    } else if (tid >= 64 && tid < 64 + 36) {
        int idx = tid - 64;
        int k = idx >> 1, which = idx & 1;
        int cen = (k < 9) ? A : jlA(k - 9, A);
        float v0=0,v1=0,v2=0,v3=0;
        #pragma unroll
        for (int hh = 0; hh < HIDDEN; hh++) {
            float u = (which ? U2[k][hh] : U1[k][hh]) * f1a[cen][hh];
            float4 w = *(const float4*)&W2s[hh][0];
            v0 = fmaf(u, w.x, v0); v1 = fmaf(u, w.y, v1);
            v2 = fmaf(u, w.z, v2); v3 = fmaf(u, w.w, v3);
        }
        if (which) { V2[k][0]=v0; V2[k][1]=v1; V2[k][2]=v2; V2[k][3]=v3; }
        else       { V1[k][0]=v0; V1[k][1]=v1; V1[k][2]=v2; V1[k][3]=v3; }
    } else if (tid >= 128 && tid < 128 + 9) {
        int k9 = tid - 128;
        int cen = jlA(k9, A);
        float q0=0,q1=0,q2=0,q3=0;
        #pragma unroll
        for (int hh = 0; hh < HIDDEN; hh++) {
            float u = U1[9+k9][hh];
            float cf = f2a[cen][hh] * u * u;
            float4 w = *(const float4*)&W2s[hh][0];
            q0 = fmaf(cf, w.x, q0); q1 = fmaf(cf, w.y, q1);
            q2 = fmaf(cf, w.z, q2); q3 = fmaf(cf, w.w, q3);
        }
        Qn[k9][0]=q0; Qn[k9][1]=q1; Qn[k9][2]=q2; Qn[k9][3]=q3;
    }
    __syncthreads();

    // -------- P6: directions (warps 0-2) + Tval (warp 3) --------
    const int w    = tid >> 5;
    const int lane = tid & 31;
    if (tid >= 96 && tid < 96 + NSTATES) {
        int s = tid - 96;
        float acc = 0.f;
        #pragma unroll
        for (int j = 0; j < NATOMS; j++)
            acc = fmaf(pv[j][s], Rr[j], acc);
        Tval[s] = acc;
    }
    if (w < 3) {
        const int mu = w;
        // perturbed atom A: quadratic tanh cross term
        float q0=0,q1=0,q2=0,q3=0;
        #pragma unroll
        for (int rep = 0; rep < 2; rep++) {
            int hh = lane + rep*32;
            if (hh < HIDDEN) {
                float ud = 0.f;
                #pragma unroll
                for (int k = 0; k < 9; k++)
                    ud = fmaf(wdd[mu][k], U1[k][hh], ud);
                float cf = f2a[A][hh] * ud * ud;
                float4 wv = *(const float4*)&W2s[hh][0];
                q0 = fmaf(cf, wv.x, q0); q1 = fmaf(cf, wv.y, q1);
                q2 = fmaf(cf, wv.z, q2); q3 = fmaf(cf, wv.w, q3);
            }
        }
        #pragma unroll
        for (int off = 16; off > 0; off >>= 1) {
            q0 += __shfl_xor_sync(FULLM, q0, off);
            q1 += __shfl_xor_sync(FULLM, q1, off);
            q2 += __shfl_xor_sync(FULLM, q2, off);
            q3 += __shfl_xor_sync(FULLM, q3, off);
        }
        float accA = 0.f;
        if (lane < 8) {
            int s = lane & 3;
            bool second = lane >= 4;
            #pragma unroll
            for (int k = 0; k < 9; k++) {
                float dd = wdd[mu][k], dh = wdh[mu][k];
                accA += second ? fmaf(dd*dd, V2[k][s], dh*V1[k][s])
                               : dd*V1[k][s];
            }
        }
        {
            float qsel = ((lane & 3)==0) ? q0 : ((lane & 3)==1) ? q1
                        : ((lane & 3)==2) ? q2 : q3;
            if (lane < 4)      wpd[mu][A][lane]   = accA;
            else if (lane < 8) wph[mu][A][lane-4] = accA + qsel;
        }
        __syncwarp();

        // the 9 neighbor atoms
        #pragma unroll
        for (int base = 0; base < 36; base += 32) {
            int item = base + lane;
            if (item < 36) {
                int k9 = item >> 2, s = item & 3;
                int kk = 9 + k9;
                float dd = wdd[mu][kk], dh = wdh[mu][kk];
                float pd = dd * V1[kk][s];
                float ph = dd*dd*(V2[kk][s] + Qn[k9][s]) + dh*V1[kk][s];
                int at = jlA(k9, A);
                wpd[mu][at][s] = pd;
                wph[mu][at][s] = ph;
            }
        }
        __syncwarp();

        // assemble T' and T''
        {
            int s = lane & 3, g = lane >> 2;
            float td = 0.f, th = 0.f;
            for (int k = g; k < 9; k += 8) {
                int j = jlA(k, A);
                float ddc = wdd[mu][k], dhc = wdh[mu][k];
                float rdc = rad1k[k]*ddc;
                float rhc = fmaf(rad2k[k], ddc*ddc, rad1k[k]*dhc);
                td = fmaf(pv[j][s], rdc, td);
                th = fmaf(2.f*wpd[mu][j][s], rdc, fmaf(pv[j][s], rhc, th));
                float ddn = wdd[mu][9+k], dhn = wdh[mu][9+k];
                float rdn = rad1k[9+k]*ddn;
                float rhn = fmaf(rad2k[9+k], ddn*ddn, rad1k[9+k]*dhn);
                td = fmaf(pv[A][s], rdn, td);
                th = fmaf(2.f*wpd[mu][A][s], rdn, fmaf(pv[A][s], rhn, th));
            }
            for (int at = g; at < NATOMS; at += 8) {
                td = fmaf(wpd[mu][at][s], Rr[at], td);
                th = fmaf(wph[mu][at][s], Rr[at], th);
            }
            #pragma unroll
            for (int off = 4; off < 32; off <<= 1) {
                td += __shfl_xor_sync(FULLM, td, off);
                th += __shfl_xor_sync(FULLM, th, off);
            }
            if (lane < 4) {
                Bsh[mu][lane] = td;
                Hsh[mu][lane] = th;
            }
        }
    }
    __syncthreads();

    // -------- P7: warp-0-only tail (warps 1-7 exit) --------
    if (tid >= 32) return;
    const int s = tid & 3;
    if (tid < NSTATES) {
        float T0 = Tval[0];
        float acc = 0.f;
        #pragma unroll
        for (int mu = 0; mu < 3; mu++) {
            float Bv = Bsh[mu][s], Hv = Hsh[mu][s];
            acc += (s == 0) ? (2.f*Bv*Bv + 2.f*T0*Hv) : Hv;
        }
        g_kin[(c*NATOMS + A)*NSTATES + s] = s_mass * acc;
        if (A == 0) g_T[c*NSTATES + s] = Tval[s];
    }
    __threadfence();
    __syncwarp();
    int flag = 0;
    if (tid == 0) flag = (atomicAdd(&g_cfg[c], 1) == NATOMS - 1);
    flag = __shfl_sync(FULLM, flag, 0);
    if (!flag) return;
    if (tid == 0) g_cfg[c] = 0;   // reset for next graph replay
    __threadfence();
    volatile float* gk = g_kin;
    volatile float* gt = g_T;
    float kin = 0.f;
    #pragma unroll
    for (int a = 0; a < NATOMS; a++)
        kin += gk[(c*NATOMS + a)*NSTATES + s];
    kin *= -0.5f;
    float Ts = gt[c*NSTATES + s];
    float T0 = __shfl_sync(FULLM, Ts, 0);
    float psi = (s == 0) ? T0*T0 : Ts;
    float vib = (kin + psi*s_pe) / psi;
    float dvv = vib - s_el[s];
    float l = dvv*dvv;
    l += __shfl_xor_sync(FULLM, l, 1);
    l += __shfl_xor_sync(FULLM, l, 2);
    if (tid == 0) {
        g_part[c] = l;
        __threadfence();
        if (atomicAdd(&g_fin, 1) == NCONF - 1) {
            g_fin = 0;   // reset for next graph replay
            __threadfence();
            volatile float* gp = g_part;
            float acc = 0.f;
            #pragma unroll
            for (int i = 0; i < NCONF; i++) acc += gp[i];
            out[0] = acc;
        }
    }
}

extern "C" void kernel_launch(void* const* d_in, const int* in_sizes, int n_in,
                              void* d_out, int out_size)
{
    // metadata order: eigen_weight, pot, cart, numatoms, species, massrev,
    //                 atom_index, shifts, W1, B1, W2, Emb, elevel
    const float* pot     = (const float*)d_in[1];
    const float* cart    = (const float*)d_in[2];
    const int*   species = (const int*)  d_in[4];
    const float* massrev = (const float*)d_in[5];
    const float* W1      = (const float*)d_in[8];
    const float* B1      = (const float*)d_in[9];
    const float* W2      = (const float*)d_in[10];
    const float* Emb     = (const float*)d_in[11];
    const float* elevel  = (const float*)d_in[12];

    fused_kernel<<<NBLOCKS, NT>>>(pot, cart, species, massrev,
                                  W1, B1, W2, Emb, elevel, (float*)d_out);
}

// round 6
// speedup vs baseline: 1.4975x; 1.1600x over previous
#include <cuda_runtime.h>

#define NCONF   8
#define NATOMS  10
#define NSTATES 4
#define NBASIS  24
#define HIDDEN  48
#define NTYPES  4
#define PPC     90            // ordered pairs, contiguous: p = i*9 + (j - (j>i))
#define NT      256
#define NBLOCKS (NCONF*NATOMS)

#define PI_F 3.14159265358979323846f
#define CUT  6.0f
#define KARG (PI_F/CUT)
#define AL   1.5f
#define DLT  (CUT/23.0f)
#define FULLM 0xffffffffu

// cross-block scratch (no cudaMalloc allowed)
__device__ float g_kin[NCONF*NATOMS*NSTATES];
__device__ float g_T[NCONF*NSTATES];
__device__ int   g_fin;

__device__ __forceinline__ int jlA(int t, int A) { return t + (t >= A); }

__device__ __forceinline__ float fast_tanh(float u) {
    float ex = __expf(2.f*u);
    return 1.f - __fdividef(2.f, ex + 1.f);
}

__global__ void __launch_bounds__(NT, 1)
fused_kernel(const float* __restrict__ pot, const float* __restrict__ cart,
             const int* __restrict__ species, const float* __restrict__ massrev,
             const float* __restrict__ W1, const float* __restrict__ B1,
             const float* __restrict__ W2, const float* __restrict__ Emb,
             const float* __restrict__ elevel, float* __restrict__ out)
{
    __shared__ __align__(16) float W1s[NBASIS][52];
    __shared__ __align__(16) float W2s[HIDDEN][4];
    __shared__ float B1all[NTYPES][48];
    __shared__ float EmbAll[NTYPES][4];
    __shared__ int   s_sp[NATOMS];
    __shared__ float s_cart[NATOMS*3];
    __shared__ float s_pe, s_mass, s_el[4];
    __shared__ float G0[PPC][25];
    __shared__ float radv[PPC];
    __shared__ float G1k[18][25], G2k[18][25];
    __shared__ float rad1k[18], rad2k[18];
    __shared__ float wdd[3][18], wdh[3][18];
    __shared__ float densv[NATOMS][25];
    __shared__ float Rr[NATOMS];
    __shared__ float tval[NATOMS][49], f1a[NATOMS][49], f2a[NATOMS][49];
    __shared__ __align__(16) float U1[18][52], U2[18][52];
    __shared__ float pv[NATOMS][4];
    __shared__ float V1[18][4], V2[18][4], Qn[9][4];
    __shared__ float wpd[3][NATOMS][4], wph[3][NATOMS][4];
    __shared__ float Tval[4];
    __shared__ float Bsh[3][4], Hsh[3][4];

    const int tid = threadIdx.x;
    const int c   = blockIdx.x / NATOMS;
    const int A   = blockIdx.x % NATOMS;

    // -------- P1: all global loads up front, no dependent chains --------
    for (int i = tid; i < NBASIS*HIDDEN; i += NT)
        W1s[i / HIDDEN][i % HIDDEN] = W1[i];
    if (tid < HIDDEN*NSTATES) {
        W2s[tid >> 2][tid & 3] = W2[tid];
        B1all[tid / 48][tid % 48] = B1[tid];        // all 4 species rows
    } else if (tid < 192 + NTYPES*NSTATES) {
        int i = tid - 192;
        EmbAll[i >> 2][i & 3] = Emb[i];
    } else if (tid < 208 + NATOMS) {
        s_sp[tid - 208] = species[c*NATOMS + (tid - 208)];
    } else if (tid >= 218 && tid < 218 + NATOMS*3) {
        s_cart[tid - 218] = cart[c*NATOMS*3 + (tid - 218)];
    } else if (tid == 248) {
        s_mass = massrev[c*NATOMS + A];
    } else if (tid == 249) {
        s_pe = pot[c] - pot[NCONF-1];
    } else if (tid >= 250 && tid < 250 + NSTATES) {
        s_el[tid - 250] = elevel[tid - 250];
    }
    __syncthreads();

    // -------- P2: pair geometry + single-pass rbf recurrence --------
    if (tid < PPC) {
        const int p = tid;
        const int i = p / 9, jr = p % 9;
        const int j = jr + (jr >= i);
        float dx = s_cart[j*3+0] - s_cart[i*3+0];
        float dy = s_cart[j*3+1] - s_cart[i*3+1];
        float dz = s_cart[j*3+2] - s_cart[i*3+2];
        float d2 = fmaf(dx, dx, fmaf(dy, dy, dz*dz));
        float d  = sqrtf(d2);
        float arg = d * KARG;
        float sn = __sinf(arg), cs = __cosf(arg);
        radv[p] = sn*sn*sn;
        float f0, fd1, fd2;
        if (d < CUT) {
            f0  = 0.5f*(cs + 1.f);
            fd1 = -0.5f*KARG*sn;
            fd2 = -0.5f*KARG*KARG*cs;
        } else { f0 = 0.f; fd1 = 0.f; fd2 = 0.f; }

        const bool isC = (i == A), isN = (j == A);
        const bool isA = isC || isN;
        const int  k   = isC ? (j - (j > A)) : (isN ? (9 + (i - (i > A))) : 0);

        // rbf(b) = exp(-AL*(d-b*DLT)^2) via geometric recurrence (2 expf total)
        const float gg = __expf(-2.f*AL*DLT*DLT);
        float rb = __expf(-AL*d2);
        float tc = __expf(fmaf(2.f*AL*DLT, d, -AL*DLT*DLT));
        #pragma unroll
        for (int b = 0; b < NBASIS; b++) {
            G0[p][b] = rb * f0;
            if (isA) {
                float t  = d - (float)b*DLT;
                float r1 = -2.f*AL*t*rb;
                float r2 = (4.f*AL*AL*t*t - 2.f*AL)*rb;
                G1k[k][b] = r1*f0 + rb*fd1;
                G2k[k][b] = r2*f0 + 2.f*r1*fd1 + rb*fd2;
            }
            rb *= tc; tc *= gg;
        }
        if (isA) {
            rad1k[k] = 3.f*sn*sn*cs * KARG;
            rad2k[k] = (6.f*sn*cs*cs - 3.f*sn*sn*sn) * (KARG*KARG);
            float invd = __frcp_rn(d);
            float sgn = isC ? -1.f : 1.f;
            float ex = dx*invd, ey = dy*invd, ez = dz*invd;
            wdd[0][k] = sgn*ex; wdh[0][k] = (1.f - ex*ex)*invd;
            wdd[1][k] = sgn*ey; wdh[1][k] = (1.f - ey*ey)*invd;
            wdd[2][k] = sgn*ez; wdh[2][k] = (1.f - ez*ez)*invd;
        }
    }
    __syncthreads();

    // -------- P3: densv, Rr, U1/U2 --------
    for (int it = tid; it < NATOMS*NBASIS + NATOMS; it += NT) {
        if (it < NATOMS*NBASIS) {
            int at = it / NBASIS, b = it % NBASIS;
            float a0 = 0.f, a1 = 0.f;
            #pragma unroll
            for (int r = 0; r < 8; r += 2) {
                a0 += G0[at*9 + r][b];
                a1 += G0[at*9 + r + 1][b];
            }
            densv[at][b] = a0 + a1 + G0[at*9 + 8][b];
        } else {
            int at = it - NATOMS*NBASIS;
            float r = 0.f;
            #pragma unroll
            for (int j = 0; j < NATOMS; j++)
                if (j != at) r += radv[j*9 + (at - (at > j))];
            Rr[at] = r;
        }
    }
    if (tid < 18*12) {   // U1/U2, hh quad-blocked, 8 independent chains
        int k = tid / 12, hq = (tid % 12) * 4;
        float a0=0,a1=0,a2=0,a3=0,b0=0,b1=0,b2=0,b3=0;
        #pragma unroll
        for (int b = 0; b < NBASIS; b++) {
            float g1 = G1k[k][b], g2 = G2k[k][b];
            float4 w = *(const float4*)&W1s[b][hq];
            a0 = fmaf(g1, w.x, a0); a1 = fmaf(g1, w.y, a1);
            a2 = fmaf(g1, w.z, a2); a3 = fmaf(g1, w.w, a3);
            b0 = fmaf(g2, w.x, b0); b1 = fmaf(g2, w.y, b1);
            b2 = fmaf(g2, w.z, b2); b3 = fmaf(g2, w.w, b3);
        }
        U1[k][hq]=a0; U1[k][hq+1]=a1; U1[k][hq+2]=a2; U1[k][hq+3]=a3;
        U2[k][hq]=b0; U2[k][hq+1]=b1; U2[k][hq+2]=b2; U2[k][hq+3]=b3;
    }
    __syncthreads();

    // -------- P4: tanh value path (4-way split accumulation) --------
    for (int it = tid; it < NATOMS*HIDDEN; it += NT) {
        int at = it / HIDDEN, hh = it % HIDDEN;
        float u0 = B1all[s_sp[at]][hh], u1 = 0.f, u2 = 0.f, u3 = 0.f;
        #pragma unroll
        for (int b = 0; b < NBASIS; b += 4) {
            u0 = fmaf(densv[at][b  ], W1s[b  ][hh], u0);
            u1 = fmaf(densv[at][b+1], W1s[b+1][hh], u1);
            u2 = fmaf(densv[at][b+2], W1s[b+2][hh], u2);
            u3 = fmaf(densv[at][b+3], W1s[b+3][hh], u3);
        }
        float t  = fast_tanh((u0 + u1) + (u2 + u3));
        float f1 = 1.f - t*t;
        tval[at][hh] = t;
        f1a[at][hh]  = f1;
        f2a[at][hh]  = -2.f*t*f1;
    }
    __syncthreads();

    // -------- P5: pv, V1/V2, Qn (2-way split chains) --------
    if (tid < NATOMS*NSTATES) {
        int at = tid >> 2, s = tid & 3;
        float a0 = EmbAll[s_sp[at]][s], a1 = 0.f;
        #pragma unroll
        for (int hh = 0; hh < HIDDEN; hh += 2) {
            a0 = fmaf(tval[at][hh  ], W2s[hh  ][s], a0);
            a1 = fmaf(tval[at][hh+1], W2s[hh+1][s], a1);
        }
        pv[at][s] = a0 + a1;
    } else if (tid >= 64 && tid < 64 + 36) {
        int idx = tid - 64;
        int k = idx >> 1, which = idx & 1;
        int cen = (k < 9) ? A : jlA(k - 9, A);
        float v0=0,v1=0,v2=0,v3=0, w0=0,w1=0,w2=0,w3=0;
        #pragma unroll
        for (int hh = 0; hh < HIDDEN; hh += 2) {
            float ua = (which ? U2[k][hh  ] : U1[k][hh  ]) * f1a[cen][hh  ];
            float ub = (which ? U2[k][hh+1] : U1[k][hh+1]) * f1a[cen][hh+1];
            float4 wa = *(const float4*)&W2s[hh  ][0];
            float4 wb = *(const float4*)&W2s[hh+1][0];
            v0 = fmaf(ua, wa.x, v0); v1 = fmaf(ua, wa.y, v1);
            v2 = fmaf(ua, wa.z, v2); v3 = fmaf(ua, wa.w, v3);
            w0 = fmaf(ub, wb.x, w0); w1 = fmaf(ub, wb.y, w1);
            w2 = fmaf(ub, wb.z, w2); w3 = fmaf(ub, wb.w, w3);
        }
        if (which) { V2[k][0]=v0+w0; V2[k][1]=v1+w1; V2[k][2]=v2+w2; V2[k][3]=v3+w3; }
        else       { V1[k][0]=v0+w0; V1[k][1]=v1+w1; V1[k][2]=v2+w2; V1[k][3]=v3+w3; }
    } else if (tid >= 128 && tid < 128 + 9) {
        int k9 = tid - 128;
        int cen = jlA(k9, A);
        float q0=0,q1=0,q2=0,q3=0, r0=0,r1=0,r2=0,r3=0;
        #pragma unroll
        for (int hh = 0; hh < HIDDEN; hh += 2) {
            float ua = U1[9+k9][hh  ];
            float ub = U1[9+k9][hh+1];
            float ca = f2a[cen][hh  ] * ua * ua;
            float cb = f2a[cen][hh+1] * ub * ub;
            float4 wa = *(const float4*)&W2s[hh  ][0];
            float4 wb = *(const float4*)&W2s[hh+1][0];
            q0 = fmaf(ca, wa.x, q0); q1 = fmaf(ca, wa.y, q1);
            q2 = fmaf(ca, wa.z, q2); q3 = fmaf(ca, wa.w, q3);
            r0 = fmaf(cb, wb.x, r0); r1 = fmaf(cb, wb.y, r1);
            r2 = fmaf(cb, wb.z, r2); r3 = fmaf(cb, wb.w, r3);
        }
        Qn[k9][0]=q0+r0; Qn[k9][1]=q1+r1; Qn[k9][2]=q2+r2; Qn[k9][3]=q3+r3;
    }
    __syncthreads();

    // -------- P6: directions (warps 0-2) + Tval (warp 3) --------
    const int w    = tid >> 5;
    const int lane = tid & 31;
    if (tid >= 96 && tid < 96 + NSTATES) {
        int s = tid - 96;
        float acc = 0.f;
        #pragma unroll
        for (int j = 0; j < NATOMS; j++)
            acc = fmaf(pv[j][s], Rr[j], acc);
        Tval[s] = acc;
    }
    if (w < 3) {
        const int mu = w;
        // perturbed atom A: quadratic tanh cross term
        float q0=0,q1=0,q2=0,q3=0;
        #pragma unroll
        for (int rep = 0; rep < 2; rep++) {
            int hh = lane + rep*32;
            if (hh < HIDDEN) {
                float ud = 0.f;
                #pragma unroll
                for (int k = 0; k < 9; k++)
                    ud = fmaf(wdd[mu][k], U1[k][hh], ud);
                float cf = f2a[A][hh] * ud * ud;
                float4 wv = *(const float4*)&W2s[hh][0];
                q0 = fmaf(cf, wv.x, q0); q1 = fmaf(cf, wv.y, q1);
                q2 = fmaf(cf, wv.z, q2); q3 = fmaf(cf, wv.w, q3);
            }
        }
        #pragma unroll
        for (int off = 16; off > 0; off >>= 1) {
            q0 += __shfl_xor_sync(FULLM, q0, off);
            q1 += __shfl_xor_sync(FULLM, q1, off);
            q2 += __shfl_xor_sync(FULLM, q2, off);
            q3 += __shfl_xor_sync(FULLM, q3, off);
        }
        float accA = 0.f;
        if (lane < 8) {
            int s = lane & 3;
            bool second = lane >= 4;
            #pragma unroll
            for (int k = 0; k < 9; k++) {
                float dd = wdd[mu][k], dh = wdh[mu][k];
                accA += second ? fmaf(dd*dd, V2[k][s], dh*V1[k][s])
                               : dd*V1[k][s];
            }
        }
        {
            float qsel = ((lane & 3)==0) ? q0 : ((lane & 3)==1) ? q1
                        : ((lane & 3)==2) ? q2 : q3;
            if (lane < 4)      wpd[mu][A][lane]   = accA;
            else if (lane < 8) wph[mu][A][lane-4] = accA + qsel;
        }
        __syncwarp();

        #pragma unroll
        for (int base = 0; base < 36; base += 32) {
            int item = base + lane;
            if (item < 36) {
                int k9 = item >> 2, s = item & 3;
                int kk = 9 + k9;
                float dd = wdd[mu][kk], dh = wdh[mu][kk];
                float pd = dd * V1[kk][s];
                float ph = dd*dd*(V2[kk][s] + Qn[k9][s]) + dh*V1[kk][s];
                int at = jlA(k9, A);
                wpd[mu][at][s] = pd;
                wph[mu][at][s] = ph;
            }
        }
        __syncwarp();

        {
            int s = lane & 3, g = lane >> 2;
            float td = 0.f, th = 0.f;
            for (int k = g; k < 9; k += 8) {
                int j = jlA(k, A);
                float ddc = wdd[mu][k], dhc = wdh[mu][k];
                float rdc = rad1k[k]*ddc;
                float rhc = fmaf(rad2k[k], ddc*ddc, rad1k[k]*dhc);
                td = fmaf(pv[j][s], rdc, td);
                th = fmaf(2.f*wpd[mu][j][s], rdc, fmaf(pv[j][s], rhc, th));
                float ddn = wdd[mu][9+k], dhn = wdh[mu][9+k];
                float rdn = rad1k[9+k]*ddn;
                float rhn = fmaf(rad2k[9+k], ddn*ddn, rad1k[9+k]*dhn);
                td = fmaf(pv[A][s], rdn, td);
                th = fmaf(2.f*wpd[mu][A][s], rdn, fmaf(pv[A][s], rhn, th));
            }
            for (int at = g; at < NATOMS; at += 8) {
                td = fmaf(wpd[mu][at][s], Rr[at], td);
                th = fmaf(wph[mu][at][s], Rr[at], th);
            }
            #pragma unroll
            for (int off = 4; off < 32; off <<= 1) {
                td += __shfl_xor_sync(FULLM, td, off);
                th += __shfl_xor_sync(FULLM, th, off);
            }
            if (lane < 4) {
                Bsh[mu][lane] = td;
                Hsh[mu][lane] = th;
            }
        }
    }
    __syncthreads();

    // -------- P7: single-level tail, warp 0 only --------
    if (tid >= 32) return;
    if (tid < NSTATES) {
        int s = tid;
        float T0 = Tval[0];
        float acc = 0.f;
        #pragma unroll
        for (int mu = 0; mu < 3; mu++) {
            float Bv = Bsh[mu][s], Hv = Hsh[mu][s];
            acc += (s == 0) ? (2.f*Bv*Bv + 2.f*T0*Hv) : Hv;
        }
        g_kin[(c*NATOMS + A)*NSTATES + s] = s_mass * acc;
        if (A == 0) g_T[c*NSTATES + s] = Tval[s];
    }
    __threadfence();
    __syncwarp();
    int flag = 0;
    if (tid == 0) flag = (atomicAdd(&g_fin, 1) == NBLOCKS - 1);
    flag = __shfl_sync(FULLM, flag, 0);
    if (!flag) return;
    __threadfence();
    // lane = (config, state): cc = tid>>2, s = tid&3  (32 lanes = 8x4)
    const int cc = tid >> 2, s = tid & 3;
    volatile float* gk = g_kin;
    volatile float* gt = g_T;
    float kin = 0.f;
    #pragma unroll
    for (int a = 0; a < NATOMS; a++)
        kin += gk[(cc*NATOMS + a)*NSTATES + s];
    kin *= -0.5f;
    float Ts = gt[cc*NSTATES + s];
    float T0 = __shfl_sync(FULLM, Ts, tid & ~3);
    float psi = (s == 0) ? T0*T0 : Ts;
    float pe  = pot[cc] - pot[NCONF-1];
    float vib = (kin + psi*pe) / psi;
    float dvv = vib - s_el[s];
    float l = dvv*dvv;
    #pragma unroll
    for (int off = 16; off > 0; off >>= 1)
        l += __shfl_xor_sync(FULLM, l, off);
    if (tid == 0) {
        out[0] = l;
        g_fin = 0;   // reset for next graph replay
    }
}

extern "C" void kernel_launch(void* const* d_in, const int* in_sizes, int n_in,
                              void* d_out, int out_size)
{
    // metadata order: eigen_weight, pot, cart, numatoms, species, massrev,
    //                 atom_index, shifts, W1, B1, W2, Emb, elevel
    const float* pot     = (const float*)d_in[1];
    const float* cart    = (const float*)d_in[2];
    const int*   species = (const int*)  d_in[4];
    const float* massrev = (const float*)d_in[5];
    const float* W1      = (const float*)d_in[8];
    const float* B1      = (const float*)d_in[9];
    const float* W2      = (const float*)d_in[10];
    const float* Emb     = (const float*)d_in[11];
    const float* elevel  = (const float*)d_in[12];

    fused_kernel<<<NBLOCKS, NT>>>(pot, cart, species, massrev,
                                  W1, B1, W2, Emb, elevel, (float*)d_out);
}